// round 5
// baseline (speedup 1.0000x reference)
#include <cuda_runtime.h>

// ---------------- problem constants ----------------
#define Bsz 256
#define Nn  2304
#define Cc  10
#define Dd  16
#define Oo  160          // Cc*Dd
#define Ii  8

#define NCH 144                  // n-chunks
#define CNK 16                   // n per chunk  (144*16 = 2304)
#define SNK 4                    // n per W smem stage
#define BW  8                    // batches per warp
#define WPB 4                    // warps per block
#define BPB (BW*WPB)             // 32 batches per block
#define PSTR NCH

// ---------------- scratch ----------------------------------------------------
__device__ float g_P[(size_t)Bsz * PSTR * Oo];       // partial s sums (23.6 MB)
__device__ float g_s0[Bsz * Oo];
__device__ float g_s01[Bsz * Oo];

// ---------------- packed f32x2 helpers (Blackwell) ---------------------------
using u64 = unsigned long long;
__device__ __forceinline__ u64 pk(float a, float b) {
    u64 r; asm("mov.b64 %0,{%1,%2};" : "=l"(r) : "f"(a), "f"(b)); return r;
}
__device__ __forceinline__ float2 upk(u64 v) {
    float2 r; asm("mov.b64 {%0,%1},%2;" : "=f"(r.x), "=f"(r.y) : "l"(v)); return r;
}
__device__ __forceinline__ u64 fma2(u64 a, u64 b, u64 c) {
    u64 d; asm("fma.rn.f32x2 %0,%1,%2,%3;" : "=l"(d) : "l"(a), "l"(b), "l"(c)); return d;
}
#define ONE2 0x3f8000003f800000ull   // {1.0f, 1.0f}

// ---- shared helper: load this lane's packed W for capsule n from smem stage -
// slot0: o=2*lane..+1 ; slot1: o=128+... (offset 64 floats) ; slot2 (lane<16)
__device__ __forceinline__ void load_wregs(const float* wrow /* [Ii][Oo] */,
                                           int lane, bool j2,
                                           u64* w0, u64* w1, u64* w2)
{
#pragma unroll
    for (int i = 0; i < Ii; i++) {
        const float* r = wrow + i * Oo;
        w0[i] = *(const u64*)(r + 2 * lane);
        w1[i] = *(const u64*)(r + 64 + 2 * lane);
        w2[i] = j2 ? *(const u64*)(r + 128 + 2 * lane) : 0ull;
    }
}

// ---- compute packed u for one (b,n): u_s = sum_i x_i * W[n,i,slot_s] --------
__device__ __forceinline__ void compute_u(const float* __restrict__ xv,
                                          const u64* w0, const u64* w1, const u64* w2,
                                          u64& u0, u64& u1, u64& u2)
{
    const float4 xa = __ldg((const float4*)xv);
    const float4 xb = __ldg((const float4*)xv + 1);
    u64 xd[Ii];
    xd[0] = pk(xa.x, xa.x); xd[1] = pk(xa.y, xa.y);
    xd[2] = pk(xa.z, xa.z); xd[3] = pk(xa.w, xa.w);
    xd[4] = pk(xb.x, xb.x); xd[5] = pk(xb.y, xb.y);
    xd[6] = pk(xb.z, xb.z); xd[7] = pk(xb.w, xb.w);
    u0 = 0ull; u1 = 0ull; u2 = 0ull;
#pragma unroll
    for (int i = 0; i < Ii; i++) {
        u0 = fma2(xd[i], w0[i], u0);
        u1 = fma2(xd[i], w1[i], u1);
        u2 = fma2(xd[i], w2[i], u2);
    }
}

// ============ S0 pass: partial sums of u over each n-chunk ===================
__global__ __launch_bounds__(128) void k_s0(const float* __restrict__ x,
                                            const float* __restrict__ W)
{
    __shared__ float sW[SNK * Ii * Oo];          // 20 KB
    const int lane = threadIdx.x & 31;
    const int warp = threadIdx.x >> 5;
    const int b0   = blockIdx.x * BPB + warp * BW;
    const int ch   = blockIdx.y;
    const int n0   = ch * CNK;
    const bool j2  = lane < 16;

    u64 a0[BW], a1[BW], a2[BW];
#pragma unroll
    for (int bb = 0; bb < BW; bb++) { a0[bb] = 0; a1[bb] = 0; a2[bb] = 0; }

    for (int st = 0; st < CNK / SNK; st++) {
        __syncthreads();
        const float* Wsrc = W + (size_t)(n0 + st * SNK) * Ii * Oo;
        for (int idx = threadIdx.x; idx < SNK * Ii * Oo / 4; idx += 128)
            ((float4*)sW)[idx] = ((const float4*)Wsrc)[idx];
        __syncthreads();
#pragma unroll
        for (int nn = 0; nn < SNK; nn++) {
            const int n = n0 + st * SNK + nn;
            u64 w0[Ii], w1[Ii], w2[Ii];
            load_wregs(sW + nn * Ii * Oo, lane, j2, w0, w1, w2);
#pragma unroll
            for (int bb = 0; bb < BW; bb++) {
                const float* xv = x + ((size_t)(b0 + bb) * Nn + n) * Ii;
                u64 u0, u1, u2;
                compute_u(xv, w0, w1, w2, u0, u1, u2);
                a0[bb] = fma2(u0, ONE2, a0[bb]);
                a1[bb] = fma2(u1, ONE2, a1[bb]);
                a2[bb] = fma2(u2, ONE2, a2[bb]);
            }
        }
    }
#pragma unroll
    for (int bb = 0; bb < BW; bb++) {
        float2* P = (float2*)(g_P + (size_t)((b0 + bb) * PSTR + ch) * Oo);
        P[lane]      = upk(a0[bb]);
        P[lane + 32] = upk(a1[bb]);
        if (j2) P[lane + 64] = upk(a2[bb]);
    }
}

// ============ R0: s0 = 0.1 * sum_ch P + 0.1 ==================================
__global__ void k_r0(void)
{
    int idx = blockIdx.x * blockDim.x + threadIdx.x;
    if (idx >= Bsz * Oo) return;
    int b = idx / Oo, o = idx - b * Oo;
    float s = 0.f;
#pragma unroll 8
    for (int ch = 0; ch < NCH; ch++)
        s += g_P[(size_t)(b * PSTR + ch) * Oo + o];
    g_s0[idx] = 0.1f * s + 0.1f;
}

// ============ routing pass: recompute u -> softmax -> weighted partials ======
__global__ __launch_bounds__(128) void k_route(const float* __restrict__ x,
                                               const float* __restrict__ W,
                                               int use_s01)
{
    __shared__ float sW[SNK * Ii * Oo];          // 20 KB
    __shared__ float sS[BPB * Oo];               // 20 KB
    const int lane = threadIdx.x & 31;
    const int warp = threadIdx.x >> 5;
    const int b0b  = blockIdx.x * BPB;           // block's first b
    const int b0   = b0b + warp * BW;            // warp's first b
    const int ch   = blockIdx.y;
    const int n0   = ch * CNK;
    const bool j2  = lane < 16;

    // s tile for the block's 32 batches
    const float* sv = (use_s01 ? g_s01 : g_s0) + b0b * Oo;
    for (int idx = threadIdx.x; idx < BPB * Oo / 4; idx += 128)
        ((float4*)sS)[idx] = ((const float4*)sv)[idx];

    u64 a0[BW], a1[BW], a2[BW];
#pragma unroll
    for (int bb = 0; bb < BW; bb++) { a0[bb] = 0; a1[bb] = 0; a2[bb] = 0; }

    for (int st = 0; st < CNK / SNK; st++) {
        __syncthreads();
        const float* Wsrc = W + (size_t)(n0 + st * SNK) * Ii * Oo;
        for (int idx = threadIdx.x; idx < SNK * Ii * Oo / 4; idx += 128)
            ((float4*)sW)[idx] = ((const float4*)Wsrc)[idx];
        __syncthreads();
#pragma unroll
        for (int nn = 0; nn < SNK; nn++) {
            const int n = n0 + st * SNK + nn;
            u64 w0[Ii], w1[Ii], w2[Ii];
            load_wregs(sW + nn * Ii * Oo, lane, j2, w0, w1, w2);
#pragma unroll
            for (int bb = 0; bb < BW; bb++) {
                const float* xv = x + ((size_t)(b0 + bb) * Nn + n) * Ii;
                u64 u0, u1, u2;
                compute_u(xv, w0, w1, w2, u0, u1, u2);

                // logits: dot(u_s, s_s) over this lane's 2 d's
                const float* srow = sS + (warp * BW + bb) * Oo;
                float2 sr0 = *(const float2*)(srow + 2 * lane);
                float2 sr1 = *(const float2*)(srow + 64 + 2 * lane);
                float2 sr2 = j2 ? *(const float2*)(srow + 128 + 2 * lane)
                                : make_float2(0.f, 0.f);
                float2 uf0 = upk(u0), uf1 = upk(u1), uf2 = upk(u2);
                float p0 = fmaf(uf0.y, sr0.y, uf0.x * sr0.x);
                float p1 = fmaf(uf1.y, sr1.y, uf1.x * sr1.x);
                float p2 = fmaf(uf2.y, sr2.y, uf2.x * sr2.x);
                // reduce over 8-lane d-group
#pragma unroll
                for (int off = 1; off <= 4; off <<= 1) {
                    p0 += __shfl_xor_sync(0xffffffffu, p0, off);
                    p1 += __shfl_xor_sync(0xffffffffu, p1, off);
                    p2 += __shfl_xor_sync(0xffffffffu, p2, off);
                }
                if (!j2) p2 = -1e30f;
                // global max over the 10 logits
                float m = fmaxf(fmaxf(p0, p1), p2);
                m = fmaxf(m, __shfl_xor_sync(0xffffffffu, m, 8));
                m = fmaxf(m, __shfl_xor_sync(0xffffffffu, m, 16));
                float e0 = __expf(p0 - m);
                float e1 = __expf(p1 - m);
                float e2 = __expf(p2 - m);
                float s = e0 + e1 + e2;
                s += __shfl_xor_sync(0xffffffffu, s, 8);
                s += __shfl_xor_sync(0xffffffffu, s, 16);
                float inv = __fdividef(1.f, s);
                a0[bb] = fma2(pk(e0 * inv, e0 * inv), u0, a0[bb]);
                a1[bb] = fma2(pk(e1 * inv, e1 * inv), u1, a1[bb]);
                a2[bb] = fma2(pk(e2 * inv, e2 * inv), u2, a2[bb]);
            }
        }
    }
#pragma unroll
    for (int bb = 0; bb < BW; bb++) {
        float2* P = (float2*)(g_P + (size_t)((b0 + bb) * PSTR + ch) * Oo);
        P[lane]      = upk(a0[bb]);
        P[lane + 32] = upk(a1[bb]);
        if (j2) P[lane + 64] = upk(a2[bb]);
    }
}

// ============ R1: s01 = s0 + (sum_ch P + 0.1) ================================
__global__ void k_r1(void)
{
    int idx = blockIdx.x * blockDim.x + threadIdx.x;
    if (idx >= Bsz * Oo) return;
    int b = idx / Oo, o = idx - b * Oo;
    float s = 0.f;
#pragma unroll 8
    for (int ch = 0; ch < NCH; ch++)
        s += g_P[(size_t)(b * PSTR + ch) * Oo + o];
    g_s01[idx] = g_s0[idx] + (s + 0.1f);
}

// ============ R2: s2 = sum + 0.1 ; v = squash(s2) ============================
__global__ __launch_bounds__(256) void k_r2_squash(float* __restrict__ out)
{
    const int wg   = (blockIdx.x << 3) + (threadIdx.x >> 5);   // 2560 warps
    const int lane = threadIdx.x & 31;
    const int b = wg / Cc;
    const int c = wg - b * Cc;
    float s = 0.f;
    if (lane < Dd) {
#pragma unroll 8
        for (int ch = 0; ch < NCH; ch++)
            s += g_P[(size_t)(b * PSTR + ch) * Oo + c * Dd + lane];
        s += 0.1f;
    }
    float t = s * s;
#pragma unroll
    for (int off = 8; off >= 1; off >>= 1)
        t += __shfl_xor_sync(0xffffffffu, t, off);
    float nrm = sqrtf(t);
    if (lane < Dd)
        out[(b * Cc + c) * Dd + lane] = s * nrm / (1.0f + t);
}

// ============ launch =========================================================
extern "C" void kernel_launch(void* const* d_in, const int* in_sizes, int n_in,
                              void* d_out, int out_size)
{
    const float* x = (const float*)d_in[0];   // [256,2304,8]
    const float* W = (const float*)d_in[1];   // [2304,8,160]
    float* out = (float*)d_out;               // [256,10,16]

    dim3 grid(Bsz / BPB, NCH);                // 8 x 144
    k_s0<<<grid, 128>>>(x, W);
    k_r0<<<160, 256>>>();
    k_route<<<grid, 128>>>(x, W, 0);
    k_r1<<<160, 256>>>();
    k_route<<<grid, 128>>>(x, W, 1);
    k_r2_squash<<<320, 256>>>(out);
}

// round 6
// speedup vs baseline: 1.1687x; 1.1687x over previous
#include <cuda_runtime.h>

// ---------------- problem constants ----------------
#define Bsz 256
#define Nn  2304
#define Cc  10
#define Dd  16
#define Oo  160          // Cc*Dd
#define Ii  8

#define BG  64                   // batch group size (u_hat slice = 94 MB < L2)
#define K1_BT 16                 // batches per GEMM block
#define K1_NC 32                 // n per GEMM block
#define K1_CH (Nn / K1_NC)       // 72 chunks (pass-1 partials)
#define K2_NC 36                 // n per routing warp
#define K2_CH (Nn / K2_NC)       // 64 chunks (pass-2/3 partials)
#define PSTR  K1_CH              // partial-buffer chunk stride (max of 72,64)

// ---------------- scratch (static device globals; no runtime alloc) ----------
__device__ float g_uhat[(size_t)Bsz * Nn * Oo];      // full-size; only group slice hot
__device__ float g_P[(size_t)Bsz * PSTR * Oo];       // partial s sums
__device__ float g_s0[Bsz * Oo];                     // s0
__device__ float g_s01[Bsz * Oo];                    // s0 + s1  (for b2 dot)

// ============ K1: u_hat[b,n,o] = sum_i x[b,n,i] * W[n,i,o]; + partial s0 ====
__global__ __launch_bounds__(160) void k1_gemm(const float* __restrict__ x,
                                               const float* __restrict__ W,
                                               int b0g)
{
    __shared__ float xs[K1_BT][K1_NC][Ii];
    const int b0    = b0g + blockIdx.x * K1_BT;
    const int n0    = blockIdx.y * K1_NC;
    const int chunk = blockIdx.y;
    const int tid   = threadIdx.x;

    // cooperative load of x tile: [16 b][32 n][8 i]
    for (int idx = tid; idx < K1_BT * K1_NC * Ii; idx += 160) {
        int bb = idx >> 8;
        int r  = idx & 255;
        int nn = r >> 3;
        int i  = r & 7;
        xs[bb][nn][i] = x[((b0 + bb) * Nn + (n0 + nn)) * Ii + i];
    }
    __syncthreads();

    const int o = tid;              // 0..159
    float acc[K1_BT];
#pragma unroll
    for (int bb = 0; bb < K1_BT; bb++) acc[bb] = 0.f;

    for (int nn = 0; nn < K1_NC; nn++) {
        const int n = n0 + nn;
        float w[Ii];
#pragma unroll
        for (int i = 0; i < Ii; i++) w[i] = W[(n * Ii + i) * Oo + o];   // coalesced
#pragma unroll
        for (int bb = 0; bb < K1_BT; bb++) {
            float u = 0.f;
#pragma unroll
            for (int i = 0; i < Ii; i++) u = fmaf(xs[bb][nn][i], w[i], u);
            g_uhat[(size_t)((b0 + bb) * Nn + n) * Oo + o] = u;   // plain store: keep in L2
            acc[bb] += u;                                        // fixed order fp32
        }
    }
#pragma unroll
    for (int bb = 0; bb < K1_BT; bb++)
        g_P[(size_t)((b0 + bb) * PSTR + chunk) * Oo + o] = acc[bb];
}

// ============ R0: s0 = 0.1 * sum_n u_hat + 0.1  (deterministic chunk order) ==
__global__ void k_r0(int b0g)
{
    int idx = blockIdx.x * blockDim.x + threadIdx.x;     // BG*Oo threads
    if (idx >= BG * Oo) return;
    int b = b0g + idx / Oo, o = idx % Oo;
    float s = 0.f;
#pragma unroll 8
    for (int ch = 0; ch < K1_CH; ch++)
        s += g_P[(size_t)(b * PSTR + ch) * Oo + o];
    g_s0[b * Oo + o] = 0.1f * s + 0.1f;
}

// ============ routing pass: logits -> softmax -> weighted partial sums =======
// warp per (b, chunk of 36 n). Lane owns float2 slots {lane, lane+32, lane+64(<16)}
// i.e. o-pairs (2s, 2s+1). 8-lane slot group holds one c's 16 d's (2 d's per lane).
// Logit reduce: 3-round butterfly x 3 regs; softmax assembled via xor8 + xor16.
__global__ __launch_bounds__(256) void k_route(int use_s01, int b0g)
{
    const int wg   = (blockIdx.x << 3) + (threadIdx.x >> 5);   // BG*64 warps
    const int lane = threadIdx.x & 31;
    const int b    = b0g + (wg >> 6);
    const int ch   = wg & 63;
    const int n0   = ch * K2_NC;
    const bool j2v = (lane < 16);

    const float2* sv = (const float2*)((use_s01 ? g_s01 : g_s0) + b * Oo);
    float2 sr0 = sv[lane];
    float2 sr1 = sv[lane + 32];
    float2 sr2 = make_float2(0.f, 0.f);
    if (j2v) sr2 = sv[lane + 64];

    float2 a0 = make_float2(0.f, 0.f);
    float2 a1 = make_float2(0.f, 0.f);
    float2 a2 = make_float2(0.f, 0.f);

    const float2* up = (const float2*)g_uhat
                       + ((size_t)(b * Nn + n0) * Oo >> 1) + lane;
    for (int nn = 0; nn < K2_NC; nn++, up += (Oo >> 1)) {
        float2 u0 = up[0];                 // plain loads: hit L2-resident tile
        float2 u1 = up[32];
        float2 u2 = make_float2(0.f, 0.f);
        if (j2v) u2 = up[64];

        // per-lane 2-d partial logits
        float p0 = fmaf(u0.y, sr0.y, u0.x * sr0.x);
        float p1 = fmaf(u1.y, sr1.y, u1.x * sr1.x);
        float p2 = fmaf(u2.y, sr2.y, u2.x * sr2.x);
        // reduce over the 8-lane d-group
#pragma unroll
        for (int off = 1; off <= 4; off <<= 1) {
            p0 += __shfl_xor_sync(0xffffffffu, p0, off);
            p1 += __shfl_xor_sync(0xffffffffu, p1, off);
            p2 += __shfl_xor_sync(0xffffffffu, p2, off);
        }
        if (!j2v) p2 = -1e30f;     // lanes 16..31 hold no j2 class

        // global max over the 10 logits (4 groups x 3 each, masked)
        float m = fmaxf(fmaxf(p0, p1), p2);
        m = fmaxf(m, __shfl_xor_sync(0xffffffffu, m, 8));
        m = fmaxf(m, __shfl_xor_sync(0xffffffffu, m, 16));

        float e0 = __expf(p0 - m);
        float e1 = __expf(p1 - m);
        float e2 = __expf(p2 - m);  // 0 for masked lanes
        float s  = e0 + e1 + e2;
        s += __shfl_xor_sync(0xffffffffu, s, 8);
        s += __shfl_xor_sync(0xffffffffu, s, 16);   // sum over all 10
        float inv = __fdividef(1.f, s);

        float w0 = e0 * inv, w1 = e1 * inv, w2 = e2 * inv;
        a0.x = fmaf(w0, u0.x, a0.x);  a0.y = fmaf(w0, u0.y, a0.y);
        a1.x = fmaf(w1, u1.x, a1.x);  a1.y = fmaf(w1, u1.y, a1.y);
        a2.x = fmaf(w2, u2.x, a2.x);  a2.y = fmaf(w2, u2.y, a2.y);
    }

    float2* P = (float2*)(g_P + (size_t)(b * PSTR + ch) * Oo);
    P[lane]      = a0;
    P[lane + 32] = a1;
    if (j2v) P[lane + 64] = a2;
}

// ============ R1: s1 = sum + 0.1 ; s01 = s0 + s1 =============================
__global__ void k_r1(int b0g)
{
    int idx = blockIdx.x * blockDim.x + threadIdx.x;
    if (idx >= BG * Oo) return;
    int b = b0g + idx / Oo, o = idx % Oo;
    float s = 0.f;
#pragma unroll 8
    for (int ch = 0; ch < K2_CH; ch++)
        s += g_P[(size_t)(b * PSTR + ch) * Oo + o];
    g_s01[b * Oo + o] = g_s0[b * Oo + o] + (s + 0.1f);
}

// ============ R2: s2 = sum + 0.1 ; v = squash(s2) ============================
// warp per (b,c); lanes 0..15 = d
__global__ __launch_bounds__(256) void k_r2_squash(float* __restrict__ out, int b0g)
{
    const int wg   = (blockIdx.x << 3) + (threadIdx.x >> 5);   // BG*Cc warps
    const int lane = threadIdx.x & 31;
    if (wg >= BG * Cc) return;
    const int b = b0g + wg / Cc;
    const int c = wg % Cc;
    float s = 0.f;
    if (lane < Dd) {
#pragma unroll 8
        for (int ch = 0; ch < K2_CH; ch++)
            s += g_P[(size_t)(b * PSTR + ch) * Oo + c * Dd + lane];
        s += 0.1f;
    }
    float t = s * s;
#pragma unroll
    for (int off = 8; off >= 1; off >>= 1)
        t += __shfl_xor_sync(0xffffffffu, t, off);   // |s|^2 within 16-lane group
    float nrm = sqrtf(t);
    if (lane < Dd)
        out[(b * Cc + c) * Dd + lane] = s * nrm / (1.0f + t);
}

// ============ launch =========================================================
extern "C" void kernel_launch(void* const* d_in, const int* in_sizes, int n_in,
                              void* d_out, int out_size)
{
    const float* x = (const float*)d_in[0];   // [256,2304,8]
    const float* W = (const float*)d_in[1];   // [2304,8,160]
    float* out = (float*)d_out;               // [256,10,16]

    for (int g = 0; g < Bsz / BG; g++) {
        const int b0g = g * BG;
        dim3 g1(BG / K1_BT, K1_CH);                    // 4 x 72
        k1_gemm<<<g1, 160>>>(x, W, b0g);
        k_r0<<<(BG * Oo + 255) / 256, 256>>>(b0g);     // 40 blocks
        k_route<<<BG * 64 / 8, 256>>>(0, b0g);         // 512 blocks
        k_r1<<<(BG * Oo + 255) / 256, 256>>>(b0g);
        k_route<<<BG * 64 / 8, 256>>>(1, b0g);         // 512 blocks
        k_r2_squash<<<BG * Cc / 8, 256>>>(out, b0g);   // 80 blocks
    }
}

// round 7
// speedup vs baseline: 2.1725x; 1.8589x over previous
#include <cuda_runtime.h>

// ---------------- problem constants ----------------
#define Bsz 256
#define Nn  2304
#define Cc  10
#define Dd  16
#define Oo  160          // Cc*Dd
#define Ii  8

#define K1_BT 16                 // batches per GEMM block
#define K1_NC 32                 // n per GEMM block
#define K1_CH (Nn / K1_NC)       // 72 chunks (pass-1 partials)
#define K2_NC 24                 // n per routing warp
#define K2_CH (Nn / K2_NC)       // 96 chunks (pass-2/3 partials)
#define PSTR  K2_CH              // partial-buffer chunk stride (max of 72,96)

// ---------------- scratch (static device globals; no runtime alloc) ----------
__device__ float g_uhat[(size_t)Bsz * Nn * Oo];      // 377 MB fp32
__device__ float g_P[(size_t)Bsz * PSTR * Oo];       // partial s sums
__device__ float g_s0[Bsz * Oo];                     // s0
__device__ float g_s01[Bsz * Oo];                    // s0 + s1  (for b2 dot)

// ============ K1: u_hat[b,n,o] = sum_i x[b,n,i] * W[n,i,o]; + partial s0 ====
__global__ __launch_bounds__(160) void k1_gemm(const float* __restrict__ x,
                                               const float* __restrict__ W)
{
    __shared__ float xs[K1_BT][K1_NC][Ii];
    const int b0    = blockIdx.x * K1_BT;
    const int n0    = blockIdx.y * K1_NC;
    const int chunk = blockIdx.y;
    const int tid   = threadIdx.x;

    for (int idx = tid; idx < K1_BT * K1_NC * Ii; idx += 160) {
        int bb = idx >> 8;
        int r  = idx & 255;
        int nn = r >> 3;
        int i  = r & 7;
        xs[bb][nn][i] = x[((b0 + bb) * Nn + (n0 + nn)) * Ii + i];
    }
    __syncthreads();

    const int o = tid;              // 0..159
    float acc[K1_BT];
#pragma unroll
    for (int bb = 0; bb < K1_BT; bb++) acc[bb] = 0.f;

    for (int nn = 0; nn < K1_NC; nn++) {
        const int n = n0 + nn;
        float w[Ii];
#pragma unroll
        for (int i = 0; i < Ii; i++) w[i] = W[(n * Ii + i) * Oo + o];   // coalesced
#pragma unroll
        for (int bb = 0; bb < K1_BT; bb++) {
            float u = 0.f;
#pragma unroll
            for (int i = 0; i < Ii; i++) u = fmaf(xs[bb][nn][i], w[i], u);
            g_uhat[(size_t)((b0 + bb) * Nn + n) * Oo + o] = u;
            acc[bb] += u;                                               // fixed order fp32
        }
    }
#pragma unroll
    for (int bb = 0; bb < K1_BT; bb++)
        g_P[(size_t)((b0 + bb) * PSTR + chunk) * Oo + o] = acc[bb];
}

// ============ R0: s0 = 0.1 * sum_n u_hat + 0.1 ===============================
__global__ void k_r0(void)
{
    int idx = blockIdx.x * blockDim.x + threadIdx.x;
    if (idx >= Bsz * Oo) return;
    int b = idx / Oo, o = idx - b * Oo;
    float s = 0.f;
#pragma unroll 8
    for (int ch = 0; ch < K1_CH; ch++)
        s += g_P[(size_t)(b * PSTR + ch) * Oo + o];
    g_s0[idx] = 0.1f * s + 0.1f;
}

// ============ routing pass: logits -> softmax -> weighted partial sums =======
// warp per (b, chunk of 24 n). Lane owns float2 slots {lane, lane+32, lane+64(<16)}.
// Double-buffered u loads: prefetch n+1 while computing n (MLP 3 -> 6).
__global__ __launch_bounds__(256) void k_route(int use_s01)
{
    const int lane = threadIdx.x & 31;
    const int warp = threadIdx.x >> 5;
    const int ch   = (blockIdx.x << 3) + warp;     // 0..95
    const int b    = blockIdx.y;                   // 0..255
    const int n0   = ch * K2_NC;
    const bool j2v = (lane < 16);

    const float2* sv = (const float2*)((use_s01 ? g_s01 : g_s0) + b * Oo);
    float2 sr0 = sv[lane];
    float2 sr1 = sv[lane + 32];
    float2 sr2 = make_float2(0.f, 0.f);
    if (j2v) sr2 = sv[lane + 64];

    float2 a0 = make_float2(0.f, 0.f);
    float2 a1 = make_float2(0.f, 0.f);
    float2 a2 = make_float2(0.f, 0.f);

    const float2* up = (const float2*)g_uhat
                       + ((size_t)(b * Nn + n0) * Oo >> 1) + lane;

    // prologue: load n=0
    float2 u0 = up[0];
    float2 u1 = up[32];
    float2 u2 = make_float2(0.f, 0.f);
    if (j2v) u2 = up[64];

#pragma unroll 2
    for (int nn = 0; nn < K2_NC; nn++) {
        // prefetch n+1 (issues before the dependent shuffle chain below)
        float2 t0, t1, t2 = make_float2(0.f, 0.f);
        if (nn + 1 < K2_NC) {
            const float2* upn = up + (Oo >> 1);
            t0 = upn[0];
            t1 = upn[32];
            if (j2v) t2 = upn[64];
        } else {
            t0 = make_float2(0.f, 0.f);
            t1 = make_float2(0.f, 0.f);
        }
        up += (Oo >> 1);

        // per-lane 2-d partial logits
        float p0 = fmaf(u0.y, sr0.y, u0.x * sr0.x);
        float p1 = fmaf(u1.y, sr1.y, u1.x * sr1.x);
        float p2 = fmaf(u2.y, sr2.y, u2.x * sr2.x);
#pragma unroll
        for (int off = 1; off <= 4; off <<= 1) {
            p0 += __shfl_xor_sync(0xffffffffu, p0, off);
            p1 += __shfl_xor_sync(0xffffffffu, p1, off);
            p2 += __shfl_xor_sync(0xffffffffu, p2, off);
        }
        if (!j2v) p2 = -1e30f;

        float m = fmaxf(fmaxf(p0, p1), p2);
        m = fmaxf(m, __shfl_xor_sync(0xffffffffu, m, 8));
        m = fmaxf(m, __shfl_xor_sync(0xffffffffu, m, 16));

        float e0 = __expf(p0 - m);
        float e1 = __expf(p1 - m);
        float e2 = __expf(p2 - m);
        float s  = e0 + e1 + e2;
        s += __shfl_xor_sync(0xffffffffu, s, 8);
        s += __shfl_xor_sync(0xffffffffu, s, 16);
        float inv = __fdividef(1.f, s);

        float w0 = e0 * inv, w1 = e1 * inv, w2 = e2 * inv;
        a0.x = fmaf(w0, u0.x, a0.x);  a0.y = fmaf(w0, u0.y, a0.y);
        a1.x = fmaf(w1, u1.x, a1.x);  a1.y = fmaf(w1, u1.y, a1.y);
        a2.x = fmaf(w2, u2.x, a2.x);  a2.y = fmaf(w2, u2.y, a2.y);

        u0 = t0; u1 = t1; u2 = t2;
    }

    float2* P = (float2*)(g_P + (size_t)(b * PSTR + ch) * Oo);
    P[lane]      = a0;
    P[lane + 32] = a1;
    if (j2v) P[lane + 64] = a2;
}

// ============ R1: s1 = sum + 0.1 ; s01 = s0 + s1 =============================
__global__ void k_r1(void)
{
    int idx = blockIdx.x * blockDim.x + threadIdx.x;
    if (idx >= Bsz * Oo) return;
    int b = idx / Oo, o = idx - b * Oo;
    float s = 0.f;
#pragma unroll 8
    for (int ch = 0; ch < K2_CH; ch++)
        s += g_P[(size_t)(b * PSTR + ch) * Oo + o];
    g_s01[idx] = g_s0[idx] + (s + 0.1f);
}

// ============ R2: s2 = sum + 0.1 ; v = squash(s2) ============================
__global__ __launch_bounds__(256) void k_r2_squash(float* __restrict__ out)
{
    const int wg   = (blockIdx.x << 3) + (threadIdx.x >> 5);   // 2560 warps
    const int lane = threadIdx.x & 31;
    const int b = wg / Cc;
    const int c = wg - b * Cc;
    float s = 0.f;
    if (lane < Dd) {
#pragma unroll 8
        for (int ch = 0; ch < K2_CH; ch++)
            s += g_P[(size_t)(b * PSTR + ch) * Oo + c * Dd + lane];
        s += 0.1f;
    }
    float t = s * s;
#pragma unroll
    for (int off = 8; off >= 1; off >>= 1)
        t += __shfl_xor_sync(0xffffffffu, t, off);
    float nrm = sqrtf(t);
    if (lane < Dd)
        out[(b * Cc + c) * Dd + lane] = s * nrm / (1.0f + t);
}

// ============ launch =========================================================
extern "C" void kernel_launch(void* const* d_in, const int* in_sizes, int n_in,
                              void* d_out, int out_size)
{
    const float* x = (const float*)d_in[0];   // [256,2304,8]
    const float* W = (const float*)d_in[1];   // [2304,8,160]
    float* out = (float*)d_out;               // [256,10,16]

    dim3 g1(Bsz / K1_BT, K1_CH);              // 16 x 72
    dim3 gr(K2_CH / 8, Bsz);                  // 12 x 256 = 3072 blocks

    k1_gemm<<<g1, 160>>>(x, W);
    k_r0<<<160, 256>>>();
    k_r0<<<160, 256>>>();                     // canary: puts k_route at ncu's capture slot
    k_route<<<gr, 256>>>(0);                  // pass 2 (s0 -> c1 -> partial s1)
    k_r1<<<160, 256>>>();
    k_route<<<gr, 256>>>(1);                  // pass 3 (s0+s1 -> c2 -> partial s2)
    k_r2_squash<<<320, 256>>>(out);
}

// round 8
// speedup vs baseline: 2.4416x; 1.1239x over previous
#include <cuda_runtime.h>

// ---------------- problem constants ----------------
#define Bsz 256
#define Nn  2304
#define Cc  10
#define Dd  16
#define Oo  160          // Cc*Dd
#define Ii  8

#define K1_BT 16                 // batches per GEMM block
#define K1_NC 32                 // n per GEMM block
#define K1_CH (Nn / K1_NC)       // 72 chunks (pass-1 partials)
#define K2_NC 24                 // n per routing warp
#define K2_CH (Nn / K2_NC)       // 96 chunks (pass-2/3 partials)
#define PSTR  K2_CH              // partial-buffer chunk stride (max of 72,96)

// ---------------- scratch (static device globals; no runtime alloc) ----------
__device__ float g_uhat[(size_t)Bsz * Nn * Oo];      // 377 MB fp32
__device__ float g_P[(size_t)Bsz * PSTR * Oo];       // partial s sums
__device__ float g_s0[Bsz * Oo];                     // s0
__device__ float g_s01[Bsz * Oo];                    // s0 + s1  (for b2 dot)

// ============ no-op canaries (position k1 at ncu's capture slot) =============
__global__ void k_nop(void) {}

// ============ K1 v2: float4 per thread =======================================
// block 160 threads: oq = tid%40 (o-quad), grp = tid/40 selects 4 of 16 b's.
// u_hat[b,n,o] = sum_i x[b,n,i]*W[n,i,o]; also per-chunk s0 partials.
// FMA i-order identical to v1 -> bit-identical results.
__global__ __launch_bounds__(160) void k1_gemm(const float* __restrict__ x,
                                               const float* __restrict__ W)
{
    __shared__ float xs[K1_BT][K1_NC][Ii];           // 16 KB
    const int b0    = blockIdx.x * K1_BT;
    const int n0    = blockIdx.y * K1_NC;
    const int chunk = blockIdx.y;
    const int tid   = threadIdx.x;
    const int oq    = tid % 40;                      // o-quad index: o = 4*oq..4*oq+3
    const int grp   = tid / 40;                      // 0..3 -> b-subgroup

    // cooperative load of x tile: [16 b][32 n][8 i]
    for (int idx = tid; idx < K1_BT * K1_NC * Ii; idx += 160) {
        int bb = idx >> 8;
        int r  = idx & 255;
        int nn = r >> 3;
        int i  = r & 7;
        xs[bb][nn][i] = x[((b0 + bb) * Nn + (n0 + nn)) * Ii + i];
    }
    __syncthreads();

    float4 acc[4];
#pragma unroll
    for (int bb = 0; bb < 4; bb++) acc[bb] = make_float4(0.f, 0.f, 0.f, 0.f);

    for (int nn = 0; nn < K1_NC; nn++) {
        const int n = n0 + nn;
        float4 w4[Ii];
#pragma unroll
        for (int i = 0; i < Ii; i++)
            w4[i] = *(const float4*)&W[(n * Ii + i) * Oo + oq * 4];
#pragma unroll
        for (int bb = 0; bb < 4; bb++) {
            const int bloc = grp * 4 + bb;
            const float* xv = xs[bloc][nn];
            float xr[Ii];
#pragma unroll
            for (int i = 0; i < Ii; i++) xr[i] = xv[i];
            float4 u = make_float4(0.f, 0.f, 0.f, 0.f);
#pragma unroll
            for (int i = 0; i < Ii; i++) {
                u.x = fmaf(xr[i], w4[i].x, u.x);
                u.y = fmaf(xr[i], w4[i].y, u.y);
                u.z = fmaf(xr[i], w4[i].z, u.z);
                u.w = fmaf(xr[i], w4[i].w, u.w);
            }
            *(float4*)&g_uhat[(size_t)((b0 + bloc) * Nn + n) * Oo + oq * 4] = u;
            acc[bb].x += u.x;  acc[bb].y += u.y;
            acc[bb].z += u.z;  acc[bb].w += u.w;     // fixed n-order fp32
        }
    }
#pragma unroll
    for (int bb = 0; bb < 4; bb++) {
        const int bloc = grp * 4 + bb;
        *(float4*)&g_P[(size_t)((b0 + bloc) * PSTR + chunk) * Oo + oq * 4] = acc[bb];
    }
}

// ============ R0: s0 = 0.1 * sum_n u_hat + 0.1 ===============================
__global__ void k_r0(void)
{
    int idx = blockIdx.x * blockDim.x + threadIdx.x;
    if (idx >= Bsz * Oo) return;
    int b = idx / Oo, o = idx - b * Oo;
    float s = 0.f;
#pragma unroll 8
    for (int ch = 0; ch < K1_CH; ch++)
        s += g_P[(size_t)(b * PSTR + ch) * Oo + o];
    g_s0[idx] = 0.1f * s + 0.1f;
}

// ============ routing pass: logits -> softmax -> weighted partial sums =======
// warp per (b, chunk of 24 n). Lane owns float2 slots {lane, lane+32, lane+64(<16)}.
// Double-buffered u loads: prefetch n+1 while computing n.
__global__ __launch_bounds__(256) void k_route(int use_s01)
{
    const int lane = threadIdx.x & 31;
    const int warp = threadIdx.x >> 5;
    const int ch   = (blockIdx.x << 3) + warp;     // 0..95
    const int b    = blockIdx.y;                   // 0..255
    const int n0   = ch * K2_NC;
    const bool j2v = (lane < 16);

    const float2* sv = (const float2*)((use_s01 ? g_s01 : g_s0) + b * Oo);
    float2 sr0 = sv[lane];
    float2 sr1 = sv[lane + 32];
    float2 sr2 = make_float2(0.f, 0.f);
    if (j2v) sr2 = sv[lane + 64];

    float2 a0 = make_float2(0.f, 0.f);
    float2 a1 = make_float2(0.f, 0.f);
    float2 a2 = make_float2(0.f, 0.f);

    const float2* up = (const float2*)g_uhat
                       + ((size_t)(b * Nn + n0) * Oo >> 1) + lane;

    // prologue: load n=0
    float2 u0 = up[0];
    float2 u1 = up[32];
    float2 u2 = make_float2(0.f, 0.f);
    if (j2v) u2 = up[64];

#pragma unroll 2
    for (int nn = 0; nn < K2_NC; nn++) {
        float2 t0, t1, t2 = make_float2(0.f, 0.f);
        if (nn + 1 < K2_NC) {
            const float2* upn = up + (Oo >> 1);
            t0 = upn[0];
            t1 = upn[32];
            if (j2v) t2 = upn[64];
        } else {
            t0 = make_float2(0.f, 0.f);
            t1 = make_float2(0.f, 0.f);
        }
        up += (Oo >> 1);

        float p0 = fmaf(u0.y, sr0.y, u0.x * sr0.x);
        float p1 = fmaf(u1.y, sr1.y, u1.x * sr1.x);
        float p2 = fmaf(u2.y, sr2.y, u2.x * sr2.x);
#pragma unroll
        for (int off = 1; off <= 4; off <<= 1) {
            p0 += __shfl_xor_sync(0xffffffffu, p0, off);
            p1 += __shfl_xor_sync(0xffffffffu, p1, off);
            p2 += __shfl_xor_sync(0xffffffffu, p2, off);
        }
        if (!j2v) p2 = -1e30f;

        float m = fmaxf(fmaxf(p0, p1), p2);
        m = fmaxf(m, __shfl_xor_sync(0xffffffffu, m, 8));
        m = fmaxf(m, __shfl_xor_sync(0xffffffffu, m, 16));

        float e0 = __expf(p0 - m);
        float e1 = __expf(p1 - m);
        float e2 = __expf(p2 - m);
        float s  = e0 + e1 + e2;
        s += __shfl_xor_sync(0xffffffffu, s, 8);
        s += __shfl_xor_sync(0xffffffffu, s, 16);
        float inv = __fdividef(1.f, s);

        float w0 = e0 * inv, w1 = e1 * inv, w2 = e2 * inv;
        a0.x = fmaf(w0, u0.x, a0.x);  a0.y = fmaf(w0, u0.y, a0.y);
        a1.x = fmaf(w1, u1.x, a1.x);  a1.y = fmaf(w1, u1.y, a1.y);
        a2.x = fmaf(w2, u2.x, a2.x);  a2.y = fmaf(w2, u2.y, a2.y);

        u0 = t0; u1 = t1; u2 = t2;
    }

    float2* P = (float2*)(g_P + (size_t)(b * PSTR + ch) * Oo);
    P[lane]      = a0;
    P[lane + 32] = a1;
    if (j2v) P[lane + 64] = a2;
}

// ============ R1: s1 = sum + 0.1 ; s01 = s0 + s1 =============================
__global__ void k_r1(void)
{
    int idx = blockIdx.x * blockDim.x + threadIdx.x;
    if (idx >= Bsz * Oo) return;
    int b = idx / Oo, o = idx - b * Oo;
    float s = 0.f;
#pragma unroll 8
    for (int ch = 0; ch < K2_CH; ch++)
        s += g_P[(size_t)(b * PSTR + ch) * Oo + o];
    g_s01[idx] = g_s0[idx] + (s + 0.1f);
}

// ============ R2: s2 = sum + 0.1 ; v = squash(s2) ============================
__global__ __launch_bounds__(256) void k_r2_squash(float* __restrict__ out)
{
    const int wg   = (blockIdx.x << 3) + (threadIdx.x >> 5);   // 2560 warps
    const int lane = threadIdx.x & 31;
    const int b = wg / Cc;
    const int c = wg - b * Cc;
    float s = 0.f;
    if (lane < Dd) {
#pragma unroll 8
        for (int ch = 0; ch < K2_CH; ch++)
            s += g_P[(size_t)(b * PSTR + ch) * Oo + c * Dd + lane];
        s += 0.1f;
    }
    float t = s * s;
#pragma unroll
    for (int off = 8; off >= 1; off >>= 1)
        t += __shfl_xor_sync(0xffffffffu, t, off);
    float nrm = sqrtf(t);
    if (lane < Dd)
        out[(b * Cc + c) * Dd + lane] = s * nrm / (1.0f + t);
}

// ============ launch =========================================================
extern "C" void kernel_launch(void* const* d_in, const int* in_sizes, int n_in,
                              void* d_out, int out_size)
{
    const float* x = (const float*)d_in[0];   // [256,2304,8]
    const float* W = (const float*)d_in[1];   // [2304,8,160]
    float* out = (float*)d_out;               // [256,10,16]

    dim3 g1(Bsz / K1_BT, K1_CH);              // 16 x 72
    dim3 gr(K2_CH / 8, Bsz);                  // 12 x 256 = 3072 blocks

    k_nop<<<1, 32>>>();                       // canaries: put k1_gemm at ncu slot
    k_nop<<<1, 32>>>();
    k_nop<<<1, 32>>>();
    k1_gemm<<<g1, 160>>>(x, W);
    k_r0<<<160, 256>>>();
    k_route<<<gr, 256>>>(0);                  // pass 2 (s0 -> c1 -> partial s1)
    k_r1<<<160, 256>>>();
    k_route<<<gr, 256>>>(1);                  // pass 3 (s0+s1 -> c2 -> partial s2)
    k_r2_squash<<<320, 256>>>(out);
}